// round 6
// baseline (speedup 1.0000x reference)
#include <cuda_runtime.h>
#include <cuda_fp16.h>

// Problem constants (fixed by the dataset)
#define HH   512
#define WW   1024
#define HOo  512
#define WOo  1024
#define NPIX (HH * WW)          // 524288 input pixels
#define NOUT (HOo * WOo)        // 524288 output cells per plane
#define NPLANE 128              // B*C
#define CPW  4                  // cells per warp (consecutive in x)
#define WARPS 8
#define CELLS_PB (CPW * WARPS)  // 32 cells per block (one row segment)

// ---- static device scratch ----
__device__ __half g_xt[(size_t)NPIX * NPLANE]; // 128MB transposed x [pixel][plane], fp16
__device__ int    g_count[NOUT];
__device__ int    g_off[NOUT];                 // per-row-local exclusive scan
__device__ int    g_cursor[NOUT];
__device__ int    g_bsum[512];
__device__ int    g_bbase[512];                // per-row global base
__device__ int4   g_entry[NPIX];               // {anchor_x, pixel, wx_bits, wy_bits}

// ---------------------------------------------------------------
// K1: transpose x [128][NPIX] fp32 -> g_xt [NPIX][128] fp16
__global__ __launch_bounds__(256)
void transpose_k(const float* __restrict__ x) {
    __shared__ float tile[32][33];
    int p0 = blockIdx.x * 32;
    int c0 = blockIdx.y * 32;
    int tx = threadIdx.x, ty = threadIdx.y;   // block (32,8)
    #pragma unroll
    for (int i = ty; i < 32; i += 8)
        tile[i][tx] = x[(size_t)(c0 + i) * NPIX + p0 + tx];
    __syncthreads();
    #pragma unroll
    for (int i = ty; i < 32; i += 8)
        g_xt[(size_t)(p0 + i) * NPLANE + c0 + tx] = __float2half(tile[tx][i]);
}

// K2: clear counters
__global__ __launch_bounds__(256)
void clear_k() {
    int i = blockIdx.x * blockDim.x + threadIdx.x;
    if (i < NOUT) g_count[i] = 0;
}

// K3: histogram — one entry per pixel, binned by anchor (floor) cell.
__global__ __launch_bounds__(256)
void hist_k(const float2* __restrict__ smap) {
    int p = blockIdx.x * blockDim.x + threadIdx.x;
    if (p >= NPIX) return;
    float2 s = __ldg(&smap[p]);
    int x0 = (int)floorf(s.x);
    int y0 = (int)floorf(s.y);
    atomicAdd(&g_count[(y0 << 10) + x0], 1);
}

// K4a: per-1024-block (= one output row) exclusive scan; totals to g_bsum
__global__ __launch_bounds__(1024)
void scanA_k() {
    int tid = threadIdx.x;
    int cell = blockIdx.x * 1024 + tid;
    int cnt = g_count[cell];
    int lane = tid & 31, wid = tid >> 5;
    int v = cnt;
    #pragma unroll
    for (int d = 1; d < 32; d <<= 1) {
        int t = __shfl_up_sync(0xFFFFFFFFu, v, d);
        if (lane >= d) v += t;
    }
    __shared__ int wsum[32];
    if (lane == 31) wsum[wid] = v;
    __syncthreads();
    if (wid == 0) {
        int s = wsum[lane];
        #pragma unroll
        for (int d = 1; d < 32; d <<= 1) {
            int t = __shfl_up_sync(0xFFFFFFFFu, s, d);
            if (lane >= d) s += t;
        }
        wsum[lane] = s;
    }
    __syncthreads();
    int excl = v - cnt + (wid ? wsum[wid - 1] : 0);
    g_off[cell] = excl;
    g_cursor[cell] = excl;
    if (tid == 1023) g_bsum[blockIdx.x] = excl + cnt;
}

// K4b: scan the 512 row totals (single block) -> g_bbase
__global__ __launch_bounds__(512)
void scanB_k() {
    int tid = threadIdx.x;
    int lane = tid & 31, wid = tid >> 5;
    int v = g_bsum[tid];
    int x = v;
    #pragma unroll
    for (int d = 1; d < 32; d <<= 1) {
        int t = __shfl_up_sync(0xFFFFFFFFu, x, d);
        if (lane >= d) x += t;
    }
    __shared__ int ws[16];
    if (lane == 31) ws[wid] = x;
    __syncthreads();
    if (wid == 0) {
        int s = (lane < 16) ? ws[lane] : 0;
        #pragma unroll
        for (int d = 1; d < 16; d <<= 1) {
            int t = __shfl_up_sync(0xFFFFFFFFu, s, d);
            if (lane >= d) s += t;
        }
        if (lane < 16) ws[lane] = s;
    }
    __syncthreads();
    g_bbase[tid] = x - v + (wid ? ws[wid - 1] : 0);
}

// K5: scatter one entry per pixel; global position = row-local cursor + row base
__global__ __launch_bounds__(256)
void scatter_k(const float2* __restrict__ smap) {
    int p = blockIdx.x * blockDim.x + threadIdx.x;
    if (p >= NPIX) return;
    float2 s = __ldg(&smap[p]);
    float x0f = floorf(s.x), y0f = floorf(s.y);
    int x0 = (int)x0f, y0 = (int)y0f;
    float wx = s.x - x0f, wy = s.y - y0f;
    int pos = atomicAdd(&g_cursor[(y0 << 10) + x0], 1) + __ldg(&g_bbase[y0]);
    g_entry[pos] = make_int4(x0, p, __float_as_int(wx), __float_as_int(wy));
}

// K6: gather. Warp owns CPW cells x 128 planes in registers.
// Entries for BOTH contributor rows preloaded lane-cooperatively (one
// memory round-trip), y-weight folded in; rows processed in 4-wide
// software-pipelined chunks (up to 8 row loads in flight per warp).
__global__ __launch_bounds__(256)
void gather_k(float* __restrict__ out) {
    __shared__ float acc_s[CELLS_PB][NPLANE + 1];
    int tid = threadIdx.x;
    int lane = tid & 31, wid = tid >> 5;            // 8 warps
    int cell0 = blockIdx.x * CELLS_PB;              // 32-aligned -> one row
    int cy = cell0 >> 10;
    int cx0 = (cell0 & 1023) + wid * CPW;

    float a[CPW][4];
    #pragma unroll
    for (int j = 0; j < CPW; j++)
        #pragma unroll
        for (int r = 0; r < 4; r++) a[j][r] = 0.0f;

    int xs = max(cx0 - 1, 0);
    int xe = min(cx0 + CPW - 1, WOo - 2);           // anchors exist in [0,1022]

    // contributor ranges: anchor rows cy-1 (weight wy) and cy (weight 1-wy)
    int beg0 = 0, cnt0 = 0, beg1 = 0, cnt1 = 0;
    if (cy >= 1) {
        int rb = (cy - 1) << 10;
        int b = __ldg(&g_bbase[cy - 1]);
        beg0 = __ldg(&g_off[rb + xs]) + b;
        cnt0 = __ldg(&g_off[rb + xe + 1]) + b - beg0;
    }
    if (cy <= HOo - 2) {
        int rb = cy << 10;
        int b = __ldg(&g_bbase[cy]);
        beg1 = __ldg(&g_off[rb + xs]) + b;
        cnt1 = __ldg(&g_off[rb + xe + 1]) + b - beg1;
    }
    int total = cnt0 + cnt1;

    // lane-cooperative entry preload (<=32 entries in one round-trip);
    // fold the y-weight into .w so processing is range-agnostic.
    int4 emine = make_int4(0, 0, 0, 0);
    if (lane < total) {
        bool r0 = lane < cnt0;
        int idx = r0 ? (beg0 + lane) : (beg1 + lane - cnt0);
        emine = __ldg(&g_entry[idx]);
        float wy = __int_as_float(emine.w);
        emine.w = __float_as_int(r0 ? wy : (1.0f - wy));
    }
    int nproc = min(total, 32);

    auto shfl_e = [&](int k) {
        int4 e;
        e.x = __shfl_sync(0xFFFFFFFFu, emine.x, k);
        e.y = __shfl_sync(0xFFFFFFFFu, emine.y, k);
        e.z = __shfl_sync(0xFFFFFFFFu, emine.z, k);
        e.w = __shfl_sync(0xFFFFFFFFu, emine.w, k);
        return e;
    };
    auto ldrow = [&](int4 e) {
        return __ldg(reinterpret_cast<const uint2*>(
            &g_xt[(size_t)e.y * NPLANE + lane * 4]));
    };
    auto process = [&](int4 e, uint2 r) {
        float wx = __int_as_float(e.z);
        float wyv = __int_as_float(e.w);
        float omx = 1.0f - wx;
        float2 f0 = __half22float2(*reinterpret_cast<__half2*>(&r.x));
        float2 f1 = __half22float2(*reinterpret_cast<__half2*>(&r.y));
        int d = e.x - cx0;                          // -1 .. CPW-1
        #pragma unroll
        for (int j = 0; j < CPW; j++) {
            float wsel = (d == j) ? omx : ((d == j - 1) ? wx : 0.0f);
            float t = wsel * wyv;
            a[j][0] = fmaf(t, f0.x, a[j][0]);
            a[j][1] = fmaf(t, f0.y, a[j][1]);
            a[j][2] = fmaf(t, f1.x, a[j][2]);
            a[j][3] = fmaf(t, f1.y, a[j][3]);
        }
    };

    // 4-wide chunks with one-chunk row prefetch
    int4 eA[4], eB[4];
    uint2 rA[4], rB[4];
    int nA = min(nproc, 4);
    #pragma unroll
    for (int j = 0; j < 4; j++)
        if (j < nA) { eA[j] = shfl_e(j); rA[j] = ldrow(eA[j]); }

    #pragma unroll 1
    for (int base = 0; base < nproc; base += 4) {
        int nn = nproc - base - 4; nn = (nn > 4) ? 4 : ((nn < 0) ? 0 : nn);
        #pragma unroll
        for (int j = 0; j < 4; j++)
            if (j < nn) { eB[j] = shfl_e(base + 4 + j); rB[j] = ldrow(eB[j]); }
        int nc = nproc - base; nc = (nc > 4) ? 4 : nc;
        #pragma unroll
        for (int j = 0; j < 4; j++)
            if (j < nc) process(eA[j], rA[j]);
        #pragma unroll
        for (int j = 0; j < 4; j++) { eA[j] = eB[j]; rA[j] = rB[j]; }
    }

    // rare tail (total > 32): correct scalar fallback
    #pragma unroll 1
    for (int k = 32; k < total; k++) {
        bool r0k = k < cnt0;
        int idx = r0k ? (beg0 + k) : (beg1 + k - cnt0);
        int4 e = __ldg(&g_entry[idx]);
        float wy = __int_as_float(e.w);
        e.w = __float_as_int(r0k ? wy : (1.0f - wy));
        process(e, ldrow(e));
    }

    // stage to shared (plane = lane*4 + r), then coalesced writeout
    #pragma unroll
    for (int j = 0; j < CPW; j++) {
        int ci = wid * CPW + j;
        acc_s[ci][lane * 4 + 0] = a[j][0];
        acc_s[ci][lane * 4 + 1] = a[j][1];
        acc_s[ci][lane * 4 + 2] = a[j][2];
        acc_s[ci][lane * 4 + 3] = a[j][3];
    }
    __syncthreads();

    for (int idx = tid; idx < CELLS_PB * NPLANE; idx += 256) {
        int plane = idx >> 5;
        int ci = idx & (CELLS_PB - 1);
        out[(size_t)plane * NOUT + cell0 + ci] = acc_s[ci][plane];
    }
}

// ---------------------------------------------------------------
extern "C" void kernel_launch(void* const* d_in, const int* in_sizes, int n_in,
                              void* d_out, int out_size) {
    const float*  x    = (const float*)d_in[0];
    const float2* smap = (const float2*)d_in[1];
    float*        out  = (float*)d_out;

    clear_k<<<NOUT / 256, 256>>>();
    {
        dim3 b(32, 8);
        dim3 g(NPIX / 32, NPLANE / 32);
        transpose_k<<<g, b>>>(x);
    }
    hist_k<<<NPIX / 256, 256>>>(smap);
    scanA_k<<<512, 1024>>>();
    scanB_k<<<1, 512>>>();
    scatter_k<<<NPIX / 256, 256>>>(smap);
    gather_k<<<NOUT / CELLS_PB, 256>>>(out);
}

// round 7
// speedup vs baseline: 1.1318x; 1.1318x over previous
#include <cuda_runtime.h>
#include <cuda_fp16.h>

// Problem constants (fixed by the dataset)
#define HH   512
#define WW   1024
#define HOo  512
#define WOo  1024
#define NPIX (HH * WW)          // 524288 input pixels
#define NOUT (HOo * WOo)        // 524288 output cells per plane
#define NPLANE 128              // B*C
#define CPW  4                  // cells per warp (consecutive in x)
#define WARPS 8
#define CELLS_PB (CPW * WARPS)  // 32 cells per block (one row segment)

// ---- static device scratch ----
__device__ __half g_xt[(size_t)NPIX * NPLANE]; // 128MB transposed x [pixel][plane], fp16
__device__ int    g_count[NOUT];
__device__ int    g_off[NOUT];                 // per-row-local exclusive scan
__device__ int    g_cursor[NOUT];
__device__ int    g_bsum[512];
__device__ int    g_bbase[512];                // per-row global base
__device__ int4   g_entry[NPIX];               // {anchor_x, pixel, wx_bits, wy_bits}

// ---------------------------------------------------------------
// K1: transpose x [128][NPIX] fp32 -> g_xt [NPIX][128] fp16
__global__ __launch_bounds__(256)
void transpose_k(const float* __restrict__ x) {
    __shared__ float tile[32][33];
    int p0 = blockIdx.x * 32;
    int c0 = blockIdx.y * 32;
    int tx = threadIdx.x, ty = threadIdx.y;   // block (32,8)
    #pragma unroll
    for (int i = ty; i < 32; i += 8)
        tile[i][tx] = x[(size_t)(c0 + i) * NPIX + p0 + tx];
    __syncthreads();
    #pragma unroll
    for (int i = ty; i < 32; i += 8)
        g_xt[(size_t)(p0 + i) * NPLANE + c0 + tx] = __float2half(tile[tx][i]);
}

// K2: clear counters
__global__ __launch_bounds__(256)
void clear_k() {
    int i = blockIdx.x * blockDim.x + threadIdx.x;
    if (i < NOUT) g_count[i] = 0;
}

// K3: histogram — one entry per pixel, binned by anchor (floor) cell.
__global__ __launch_bounds__(256)
void hist_k(const float2* __restrict__ smap) {
    int p = blockIdx.x * blockDim.x + threadIdx.x;
    if (p >= NPIX) return;
    float2 s = __ldg(&smap[p]);
    int x0 = (int)floorf(s.x);
    int y0 = (int)floorf(s.y);
    atomicAdd(&g_count[(y0 << 10) + x0], 1);
}

// K4a: per-1024-block (= one output row) exclusive scan; totals to g_bsum
__global__ __launch_bounds__(1024)
void scanA_k() {
    int tid = threadIdx.x;
    int cell = blockIdx.x * 1024 + tid;
    int cnt = g_count[cell];
    int lane = tid & 31, wid = tid >> 5;
    int v = cnt;
    #pragma unroll
    for (int d = 1; d < 32; d <<= 1) {
        int t = __shfl_up_sync(0xFFFFFFFFu, v, d);
        if (lane >= d) v += t;
    }
    __shared__ int wsum[32];
    if (lane == 31) wsum[wid] = v;
    __syncthreads();
    if (wid == 0) {
        int s = wsum[lane];
        #pragma unroll
        for (int d = 1; d < 32; d <<= 1) {
            int t = __shfl_up_sync(0xFFFFFFFFu, s, d);
            if (lane >= d) s += t;
        }
        wsum[lane] = s;
    }
    __syncthreads();
    int excl = v - cnt + (wid ? wsum[wid - 1] : 0);
    g_off[cell] = excl;
    g_cursor[cell] = excl;
    if (tid == 1023) g_bsum[blockIdx.x] = excl + cnt;
}

// K4b: scan the 512 row totals (single block) -> g_bbase
__global__ __launch_bounds__(512)
void scanB_k() {
    int tid = threadIdx.x;
    int lane = tid & 31, wid = tid >> 5;
    int v = g_bsum[tid];
    int x = v;
    #pragma unroll
    for (int d = 1; d < 32; d <<= 1) {
        int t = __shfl_up_sync(0xFFFFFFFFu, x, d);
        if (lane >= d) x += t;
    }
    __shared__ int ws[16];
    if (lane == 31) ws[wid] = x;
    __syncthreads();
    if (wid == 0) {
        int s = (lane < 16) ? ws[lane] : 0;
        #pragma unroll
        for (int d = 1; d < 16; d <<= 1) {
            int t = __shfl_up_sync(0xFFFFFFFFu, s, d);
            if (lane >= d) s += t;
        }
        if (lane < 16) ws[lane] = s;
    }
    __syncthreads();
    g_bbase[tid] = x - v + (wid ? ws[wid - 1] : 0);
}

// K5: scatter one entry per pixel; global position = row-local cursor + row base
__global__ __launch_bounds__(256)
void scatter_k(const float2* __restrict__ smap) {
    int p = blockIdx.x * blockDim.x + threadIdx.x;
    if (p >= NPIX) return;
    float2 s = __ldg(&smap[p]);
    float x0f = floorf(s.x), y0f = floorf(s.y);
    int x0 = (int)x0f, y0 = (int)y0f;
    float wx = s.x - x0f, wy = s.y - y0f;
    int pos = atomicAdd(&g_cursor[(y0 << 10) + x0], 1) + __ldg(&g_bbase[y0]);
    g_entry[pos] = make_int4(x0, p, __float_as_int(wx), __float_as_int(wy));
}

// K6: gather. Warp owns CPW cells x 128 planes in registers.
// Both contributor ranges merged into one index space; uniform 4-wide
// chunks (clamped index + arithmetically-zeroed weight for padding) with
// one-chunk prefetch -> up to 8 independent 256B row loads in flight.
__global__ __launch_bounds__(256)
void gather_k(float* __restrict__ out) {
    __shared__ float acc_s[CELLS_PB][NPLANE + 1];
    int tid = threadIdx.x;
    int lane = tid & 31, wid = tid >> 5;            // 8 warps
    int cell0 = blockIdx.x * CELLS_PB;              // 32-aligned -> one row
    int cy = cell0 >> 10;
    int cx0 = (cell0 & 1023) + wid * CPW;

    float a[CPW][4];
    #pragma unroll
    for (int j = 0; j < CPW; j++)
        #pragma unroll
        for (int r = 0; r < 4; r++) a[j][r] = 0.0f;

    int xs = max(cx0 - 1, 0);
    int xe = min(cx0 + CPW - 1, WOo - 2);           // anchors exist in [0,1022]

    // contributor ranges: anchor rows cy-1 (weight wy) and cy (weight 1-wy)
    int beg0 = 0, cnt0 = 0, beg1 = 0, cnt1 = 0;
    if (cy >= 1) {
        int rb = (cy - 1) << 10;
        int b = __ldg(&g_bbase[cy - 1]);
        beg0 = __ldg(&g_off[rb + xs]) + b;
        cnt0 = __ldg(&g_off[rb + xe + 1]) + b - beg0;
    }
    if (cy <= HOo - 2) {
        int rb = cy << 10;
        int b = __ldg(&g_bbase[cy]);
        beg1 = __ldg(&g_off[rb + xs]) + b;
        cnt1 = __ldg(&g_off[rb + xe + 1]) + b - beg1;
    }
    int total = cnt0 + cnt1;

    // entry load by merged index k; clamp + zero-weight padding keeps the
    // chunked loop fully uniform (no divergent guards).
    auto eload = [&](int k) {
        int kc = min(k, total - 1);
        bool r0 = kc < cnt0;
        int idx = r0 ? (beg0 + kc) : (beg1 + kc - cnt0);
        int4 e = __ldg(&g_entry[idx]);
        float wy = __int_as_float(e.w);
        float wyv = r0 ? wy : (1.0f - wy);
        e.w = __float_as_int((k < total) ? wyv : 0.0f);
        return e;
    };
    auto ldrow = [&](int4 e) {
        return __ldg(reinterpret_cast<const uint2*>(
            &g_xt[(size_t)e.y * NPLANE + lane * 4]));
    };
    auto process = [&](int4 e, uint2 r) {
        float wx = __int_as_float(e.z);
        float wyv = __int_as_float(e.w);
        float omx = 1.0f - wx;
        float2 f0 = __half22float2(*reinterpret_cast<__half2*>(&r.x));
        float2 f1 = __half22float2(*reinterpret_cast<__half2*>(&r.y));
        int d = e.x - cx0;                          // -1 .. CPW-1
        #pragma unroll
        for (int j = 0; j < CPW; j++) {
            float wsel = (d == j) ? omx : ((d == j - 1) ? wx : 0.0f);
            float t = wsel * wyv;
            a[j][0] = fmaf(t, f0.x, a[j][0]);
            a[j][1] = fmaf(t, f0.y, a[j][1]);
            a[j][2] = fmaf(t, f1.x, a[j][2]);
            a[j][3] = fmaf(t, f1.y, a[j][3]);
        }
    };

    if (total > 0) {
        int4 E0[4]; uint2 R0[4];
        #pragma unroll
        for (int j = 0; j < 4; j++) E0[j] = eload(j);
        #pragma unroll
        for (int j = 0; j < 4; j++) R0[j] = ldrow(E0[j]);

        #pragma unroll 1
        for (int base = 0; base < total; base += 4) {
            int4 E1[4]; uint2 R1[4];
            if (base + 4 < total) {                 // prefetch next chunk
                #pragma unroll
                for (int j = 0; j < 4; j++) E1[j] = eload(base + 4 + j);
                #pragma unroll
                for (int j = 0; j < 4; j++) R1[j] = ldrow(E1[j]);
            }
            #pragma unroll
            for (int j = 0; j < 4; j++) process(E0[j], R0[j]);
            #pragma unroll
            for (int j = 0; j < 4; j++) { E0[j] = E1[j]; R0[j] = R1[j]; }
        }
    }

    // stage to shared (plane = lane*4 + r), then coalesced writeout
    #pragma unroll
    for (int j = 0; j < CPW; j++) {
        int ci = wid * CPW + j;
        acc_s[ci][lane * 4 + 0] = a[j][0];
        acc_s[ci][lane * 4 + 1] = a[j][1];
        acc_s[ci][lane * 4 + 2] = a[j][2];
        acc_s[ci][lane * 4 + 3] = a[j][3];
    }
    __syncthreads();

    for (int idx = tid; idx < CELLS_PB * NPLANE; idx += 256) {
        int plane = idx >> 5;
        int ci = idx & (CELLS_PB - 1);
        out[(size_t)plane * NOUT + cell0 + ci] = acc_s[ci][plane];
    }
}

// ---------------------------------------------------------------
extern "C" void kernel_launch(void* const* d_in, const int* in_sizes, int n_in,
                              void* d_out, int out_size) {
    const float*  x    = (const float*)d_in[0];
    const float2* smap = (const float2*)d_in[1];
    float*        out  = (float*)d_out;

    clear_k<<<NOUT / 256, 256>>>();
    {
        dim3 b(32, 8);
        dim3 g(NPIX / 32, NPLANE / 32);
        transpose_k<<<g, b>>>(x);
    }
    hist_k<<<NPIX / 256, 256>>>(smap);
    scanA_k<<<512, 1024>>>();
    scanB_k<<<1, 512>>>();
    scatter_k<<<NPIX / 256, 256>>>(smap);
    gather_k<<<NOUT / CELLS_PB, 256>>>(out);
}